// round 1
// baseline (speedup 1.0000x reference)
#include <cuda_runtime.h>
#include <cuda_bf16.h>

#define MAX_NODES 50000
#define MAX_EDGES 800000
#define DFEAT 64

// ---- scratch (device globals; no allocation allowed) ----
__device__ int   g_deg[MAX_NODES];        // out-degree by src (for normalization)
__device__ int   g_cnt[MAX_NODES];        // in-degree by dst (for CSC build)
__device__ float g_dinv[MAX_NODES];
__device__ int   g_rowptr[MAX_NODES + 1];
__device__ int   g_cursor[MAX_NODES];
__device__ int   g_col[MAX_EDGES];
__device__ float g_w[MAX_EDGES];
__device__ float g_x1[MAX_NODES * DFEAT];
__device__ float g_x2[MAX_NODES * DFEAT];

__global__ void k_zero(int n) {
    int i = blockIdx.x * blockDim.x + threadIdx.x;
    if (i < n) { g_deg[i] = 0; g_cnt[i] = 0; }
}

__global__ void k_count(const int* __restrict__ src, const int* __restrict__ dst, int E) {
    int e = blockIdx.x * blockDim.x + threadIdx.x;
    if (e < E) {
        atomicAdd(&g_deg[src[e]], 1);
        atomicAdd(&g_cnt[dst[e]], 1);
    }
}

__global__ void k_dinv(int n) {
    int i = blockIdx.x * blockDim.x + threadIdx.x;
    if (i < n) {
        int d = g_deg[i];
        g_dinv[i] = (d > 0) ? rsqrtf((float)d) : 0.0f;
    }
}

// Single-block exclusive scan of g_cnt -> g_rowptr / g_cursor. n <= ~50k.
__global__ void k_scan(int n) {
    __shared__ int s[1024];
    int t = threadIdx.x;
    int chunk = (n + 1023) / 1024;
    int b = t * chunk;
    int e = min(n, b + chunk);
    int sum = 0;
    for (int i = b; i < e; i++) sum += g_cnt[i];
    s[t] = sum;
    __syncthreads();
    // Hillis-Steele inclusive scan over 1024 partials
    for (int off = 1; off < 1024; off <<= 1) {
        int v = (t >= off) ? s[t - off] : 0;
        __syncthreads();
        s[t] += v;
        __syncthreads();
    }
    int run = s[t] - sum;  // exclusive prefix for this thread's chunk
    for (int i = b; i < e; i++) {
        g_rowptr[i] = run;
        g_cursor[i] = run;
        run += g_cnt[i];
    }
    if (t == 0) g_rowptr[n] = s[1023];
}

__global__ void k_fill(const int* __restrict__ src, const int* __restrict__ dst, int E) {
    int e = blockIdx.x * blockDim.x + threadIdx.x;
    if (e < E) {
        int d = dst[e];
        int s = src[e];
        int pos = atomicAdd(&g_cursor[d], 1);
        g_col[pos] = s;
        g_w[pos]   = g_dinv[s] * g_dinv[d];
    }
}

// One warp per output row. Lane handles features {lane, lane+32}.
// xin_sel: 0 = feat param, 1 = g_x1, 2 = g_x2
// xout_sel: 0 = none, 1 = g_x1, 2 = g_x2
__global__ void k_spmm(const float* __restrict__ feat, float* __restrict__ h,
                       float theta, int init, int xin_sel, int xout_sel, int n) {
    int warp = (blockIdx.x * blockDim.x + threadIdx.x) >> 5;
    int lane = threadIdx.x & 31;
    if (warp >= n) return;

    const float* __restrict__ x =
        (xin_sel == 0) ? feat : ((xin_sel == 1) ? (const float*)g_x1 : (const float*)g_x2);
    float* xout = (xout_sel == 0) ? (float*)0 : ((xout_sel == 1) ? g_x1 : g_x2);

    int beg = g_rowptr[warp];
    int end = g_rowptr[warp + 1];

    float a0 = 0.0f, a1 = 0.0f;
    for (int p = beg; p < end; p++) {
        int   c  = g_col[p];
        float wv = g_w[p];
        const float* xr = x + (size_t)c * DFEAT;
        a0 = fmaf(wv, xr[lane],      a0);
        a1 = fmaf(wv, xr[lane + 32], a1);
    }

    int o = warp * DFEAT + lane;
    if (xout) {
        xout[o]      = a0;
        xout[o + 32] = a1;
    }
    if (init) {
        h[o]      = theta * a0;
        h[o + 32] = theta * a1;
    } else {
        h[o]      += theta * a0;
        h[o + 32] += theta * a1;
    }
}

extern "C" void kernel_launch(void* const* d_in, const int* in_sizes, int n_in,
                              void* d_out, int out_size) {
    const float* feat = (const float*)d_in[0];
    const int*   src  = (const int*)d_in[1];
    const int*   dst  = (const int*)d_in[2];
    float*       h    = (float*)d_out;

    int n = in_sizes[0] / DFEAT;   // 50000
    int E = in_sizes[1];           // 800000

    int tb = 256;
    int gn = (n + tb - 1) / tb;
    int ge = (E + tb - 1) / tb;

    k_zero<<<gn, tb>>>(n);
    k_count<<<ge, tb>>>(src, dst, E);
    k_dinv<<<gn, tb>>>(n);
    k_scan<<<1, 1024>>>(n);
    k_fill<<<ge, tb>>>(src, dst, E);

    // one warp per row; 8 warps per block
    int gs = (n + 7) / 8;
    // h = (theta0+theta1) * A@f            = 0.80 * x1
    k_spmm<<<gs, tb>>>(feat, h, 0.80f, 1, 0, 1, n);
    // h += theta2 * A@x1                   = 0.15 * x2
    k_spmm<<<gs, tb>>>(feat, h, 0.15f, 0, 1, 2, n);
    // h += theta3 * A@x2                   = 0.05 * x3
    k_spmm<<<gs, tb>>>(feat, h, 0.05f, 0, 2, 0, n);
}

// round 2
// speedup vs baseline: 1.7386x; 1.7386x over previous
#include <cuda_runtime.h>
#include <cuda_bf16.h>

#define MAX_NODES 50000
#define MAX_EDGES 800000
#define DFEAT 64
#define SCAN_B 1024
#define MAX_BLK ((MAX_NODES + SCAN_B - 1) / SCAN_B)

// ---- scratch (device globals; no allocation allowed) ----
__device__ int   g_deg[MAX_NODES];        // out-degree by src (for normalization)
__device__ int   g_cnt[MAX_NODES];        // in-degree by dst (for CSC build)
__device__ float g_dinv[MAX_NODES];
__device__ int   g_rowptr[MAX_NODES + 1];
__device__ int   g_cursor[MAX_NODES];
__device__ int   g_bsum[MAX_BLK];
__device__ int   g_bpref[MAX_BLK];
__device__ int   g_col[MAX_EDGES];
__device__ float g_w[MAX_EDGES];
__device__ float g_x1[MAX_NODES * DFEAT];
__device__ float g_x2[MAX_NODES * DFEAT];

__global__ void k_zero(int n) {
    int i = blockIdx.x * blockDim.x + threadIdx.x;
    if (i < n) { g_deg[i] = 0; g_cnt[i] = 0; }
}

__global__ void k_count(const int* __restrict__ src, const int* __restrict__ dst, int E) {
    int e = blockIdx.x * blockDim.x + threadIdx.x;
    if (e < E) {
        atomicAdd(&g_deg[src[e]], 1);
        atomicAdd(&g_cnt[dst[e]], 1);
    }
}

__global__ void k_dinv(int n) {
    int i = blockIdx.x * blockDim.x + threadIdx.x;
    if (i < n) {
        int d = g_deg[i];
        g_dinv[i] = (d > 0) ? rsqrtf((float)d) : 0.0f;
    }
}

// Phase 1: per-block inclusive scan of 1024 counts; writes within-block
// exclusive prefix to g_rowptr (temp) and block total to g_bsum.
__global__ void k_scan1(int n) {
    __shared__ int s[SCAN_B];
    int t = threadIdx.x;
    int i = blockIdx.x * SCAN_B + t;
    int v = (i < n) ? g_cnt[i] : 0;
    s[t] = v;
    __syncthreads();
    for (int off = 1; off < SCAN_B; off <<= 1) {
        int u = (t >= off) ? s[t - off] : 0;
        __syncthreads();
        s[t] += u;
        __syncthreads();
    }
    if (i < n) g_rowptr[i] = s[t] - v;          // exclusive within block
    if (t == SCAN_B - 1) g_bsum[blockIdx.x] = s[t];
}

// Phase 2: exclusive scan of <=49 block sums (single warp, serial is fine).
__global__ void k_scan2(int nb, int n) {
    if (threadIdx.x == 0) {
        int run = 0;
        for (int b = 0; b < nb; b++) {
            g_bpref[b] = run;
            run += g_bsum[b];
        }
        g_rowptr[n] = run;   // total edge count
    }
}

// Phase 3: add block offsets; materialize rowptr + cursor.
__global__ void k_scan3(int n) {
    int i = blockIdx.x * SCAN_B + threadIdx.x;
    if (i < n) {
        int r = g_rowptr[i] + g_bpref[blockIdx.x];
        g_rowptr[i] = r;
        g_cursor[i] = r;
    }
}

__global__ void k_fill(const int* __restrict__ src, const int* __restrict__ dst, int E) {
    int e = blockIdx.x * blockDim.x + threadIdx.x;
    if (e < E) {
        int d = dst[e];
        int s = src[e];
        int pos = atomicAdd(&g_cursor[d], 1);
        g_col[pos] = s;
        g_w[pos]   = g_dinv[s] * g_dinv[d];
    }
}

// One warp per output row. Lane handles features {lane, lane+32}.
// xin_sel: 0 = feat param, 1 = g_x1, 2 = g_x2
// xout_sel: 0 = none, 1 = g_x1, 2 = g_x2
__global__ void k_spmm(const float* __restrict__ feat, float* __restrict__ h,
                       float theta, int init, int xin_sel, int xout_sel, int n) {
    int warp = (blockIdx.x * blockDim.x + threadIdx.x) >> 5;
    int lane = threadIdx.x & 31;
    if (warp >= n) return;

    const float* __restrict__ x =
        (xin_sel == 0) ? feat : ((xin_sel == 1) ? (const float*)g_x1 : (const float*)g_x2);
    float* xout = (xout_sel == 0) ? (float*)0 : ((xout_sel == 1) ? g_x1 : g_x2);

    int beg = g_rowptr[warp];
    int end = g_rowptr[warp + 1];

    float a0 = 0.0f, a1 = 0.0f;
    int p = beg;
    // Unroll by 4: batch the col/w loads up front to raise MLP on the
    // dependent col -> x[c] gather chain.
    for (; p + 3 < end; p += 4) {
        int   c0 = g_col[p],   c1 = g_col[p + 1];
        int   c2 = g_col[p + 2], c3 = g_col[p + 3];
        float w0 = g_w[p],     w1 = g_w[p + 1];
        float w2 = g_w[p + 2], w3 = g_w[p + 3];
        const float* r0 = x + (size_t)c0 * DFEAT;
        const float* r1 = x + (size_t)c1 * DFEAT;
        const float* r2 = x + (size_t)c2 * DFEAT;
        const float* r3 = x + (size_t)c3 * DFEAT;
        float v00 = r0[lane], v01 = r0[lane + 32];
        float v10 = r1[lane], v11 = r1[lane + 32];
        float v20 = r2[lane], v21 = r2[lane + 32];
        float v30 = r3[lane], v31 = r3[lane + 32];
        a0 = fmaf(w0, v00, a0); a1 = fmaf(w0, v01, a1);
        a0 = fmaf(w1, v10, a0); a1 = fmaf(w1, v11, a1);
        a0 = fmaf(w2, v20, a0); a1 = fmaf(w2, v21, a1);
        a0 = fmaf(w3, v30, a0); a1 = fmaf(w3, v31, a1);
    }
    for (; p < end; p++) {
        int   c  = g_col[p];
        float wv = g_w[p];
        const float* xr = x + (size_t)c * DFEAT;
        a0 = fmaf(wv, xr[lane],      a0);
        a1 = fmaf(wv, xr[lane + 32], a1);
    }

    int o = warp * DFEAT + lane;
    if (xout) {
        xout[o]      = a0;
        xout[o + 32] = a1;
    }
    if (init) {
        h[o]      = theta * a0;
        h[o + 32] = theta * a1;
    } else {
        h[o]      += theta * a0;
        h[o + 32] += theta * a1;
    }
}

extern "C" void kernel_launch(void* const* d_in, const int* in_sizes, int n_in,
                              void* d_out, int out_size) {
    const float* feat = (const float*)d_in[0];
    const int*   src  = (const int*)d_in[1];
    const int*   dst  = (const int*)d_in[2];
    float*       h    = (float*)d_out;

    int n = in_sizes[0] / DFEAT;   // 50000
    int E = in_sizes[1];           // 800000

    int tb = 256;
    int gn = (n + tb - 1) / tb;
    int ge = (E + tb - 1) / tb;
    int nb = (n + SCAN_B - 1) / SCAN_B;

    k_zero<<<gn, tb>>>(n);
    k_count<<<ge, tb>>>(src, dst, E);
    k_dinv<<<gn, tb>>>(n);
    k_scan1<<<nb, SCAN_B>>>(n);
    k_scan2<<<1, 32>>>(nb, n);
    k_scan3<<<nb, SCAN_B>>>(n);
    k_fill<<<ge, tb>>>(src, dst, E);

    // one warp per row; 8 warps per block
    int gs = (n + 7) / 8;
    // h = (theta0+theta1) * A@f            = 0.80 * x1
    k_spmm<<<gs, tb>>>(feat, h, 0.80f, 1, 0, 1, n);
    // h += theta2 * A@x1                   = 0.15 * x2
    k_spmm<<<gs, tb>>>(feat, h, 0.15f, 0, 1, 2, n);
    // h += theta3 * A@x2                   = 0.05 * x3
    k_spmm<<<gs, tb>>>(feat, h, 0.05f, 0, 2, 0, n);
}